// round 2
// baseline (speedup 1.0000x reference)
#include <cuda_runtime.h>
#include <cstdio>

#define HH 128
#define WW 128
#define HWSZ (HH * WW)

// ---------------- scratch (static device arrays; no allocation) ----------------
__device__ float  g_h1[2 * 64 * HWSZ];          // conv1 out
__device__ float  g_h2[2 * 64 * HWSZ];          // conv2 out
__device__ float  g_o [2 * 432 * HWSZ];         // conv3 out (raw offsets/mask logits)
__device__ float4 g_xt[2 * 16 * HWSZ];          // x transposed to [B,G,H,W,cg=4]

// ---------------- conv 3x3, pad 1, stride 1, NCHW fp32 ----------------
// tile 32x32 output pixels, 256 threads (16x16), each thread computes 2x2 pixels
// for OCB=8 output channels. Input staged in smem CCHUNK=8 channels at a time.
constexpr int TILE = 32;
constexpr int OCB = 8;
constexpr int CCHUNK = 8;

template <bool LEAKY>
__global__ __launch_bounds__(256, 2)
void conv3x3_kernel(const float* __restrict__ in, const float* __restrict__ wgt,
                    const float* __restrict__ bias, float* __restrict__ out,
                    int Cin, int Cout) {
    __shared__ float s_in[CCHUNK][34][36];   // padded rows (36) to soften bank conflicts
    __shared__ float s_w[OCB][CCHUNK][9];

    const int tx = threadIdx.x & 15;
    const int ty = threadIdx.x >> 4;
    const int tile_id = blockIdx.x;                  // 16 tiles (4x4)
    const int ty0 = (tile_id / (WW / TILE)) * TILE;
    const int tx0 = (tile_id % (WW / TILE)) * TILE;
    const int ocb = blockIdx.y;
    const int b = blockIdx.z;

    const float* in_b = in + (size_t)b * Cin * HWSZ;

    float acc[OCB][4];
#pragma unroll
    for (int i = 0; i < OCB; i++) {
        acc[i][0] = 0.f; acc[i][1] = 0.f; acc[i][2] = 0.f; acc[i][3] = 0.f;
    }

    for (int c0 = 0; c0 < Cin; c0 += CCHUNK) {
        __syncthreads();
        // stage input chunk: CCHUNK x 34 x 34 (with zero halo)
        for (int idx = threadIdx.x; idx < CCHUNK * 34 * 34; idx += 256) {
            int ch = idx / (34 * 34);
            int rem = idx % (34 * 34);
            int r = rem / 34;
            int cc = rem % 34;
            int gy = ty0 - 1 + r;
            int gx = tx0 - 1 + cc;
            float v = 0.f;
            if (gy >= 0 && gy < HH && gx >= 0 && gx < WW)
                v = in_b[(size_t)(c0 + ch) * HWSZ + gy * WW + gx];
            s_in[ch][r][cc] = v;
        }
        // stage weights: OCB x CCHUNK x 9
        for (int idx = threadIdx.x; idx < OCB * CCHUNK * 9; idx += 256) {
            int oc = idx / (CCHUNK * 9);
            int rem = idx % (CCHUNK * 9);
            int ci = rem / 9;
            int k = rem % 9;
            s_w[oc][ci][k] = wgt[(size_t)((ocb * OCB + oc) * Cin + c0 + ci) * 9 + k];
        }
        __syncthreads();

#pragma unroll
        for (int ci = 0; ci < CCHUNK; ci++) {
            float iv[4][4];
#pragma unroll
            for (int dy = 0; dy < 4; dy++)
#pragma unroll
                for (int dx = 0; dx < 4; dx++)
                    iv[dy][dx] = s_in[ci][2 * ty + dy][2 * tx + dx];
#pragma unroll
            for (int oc = 0; oc < OCB; oc++) {
#pragma unroll
                for (int ky = 0; ky < 3; ky++)
#pragma unroll
                    for (int kx = 0; kx < 3; kx++) {
                        float w = s_w[oc][ci][ky * 3 + kx];
                        acc[oc][0] = fmaf(iv[ky][kx],         w, acc[oc][0]);
                        acc[oc][1] = fmaf(iv[ky][kx + 1],     w, acc[oc][1]);
                        acc[oc][2] = fmaf(iv[ky + 1][kx],     w, acc[oc][2]);
                        acc[oc][3] = fmaf(iv[ky + 1][kx + 1], w, acc[oc][3]);
                    }
            }
        }
    }

    const int oy = ty0 + 2 * ty;
    const int ox = tx0 + 2 * tx;
#pragma unroll
    for (int oc = 0; oc < OCB; oc++) {
        float bv = bias[ocb * OCB + oc];
        float* op = out + ((size_t)b * Cout + ocb * OCB + oc) * HWSZ;
#pragma unroll
        for (int q = 0; q < 4; q++) {
            float v = acc[oc][q] + bv;
            if (LEAKY) v = (v >= 0.f) ? v : 0.1f * v;
            int yy = oy + (q >> 1);
            int xx = ox + (q & 1);
            op[yy * WW + xx] = v;
        }
    }
}

// ---------------- x transpose: [B,64,H,W] -> [B,16,H,W,4] (channels-last in group) --
__global__ void transpose_x_kernel(const float* __restrict__ x, float4* __restrict__ xt) {
    int idx = blockIdx.x * 256 + threadIdx.x;      // over B*16*HW
    if (idx >= 2 * 16 * HWSZ) return;
    int p = idx & (HWSZ - 1);
    int bg = idx / HWSZ;                           // b*16+g
    const float* src = x + (size_t)bg * 4 * HWSZ + p;
    float4 v;
    v.x = src[0];
    v.y = src[HWSZ];
    v.z = src[2 * HWSZ];
    v.w = src[3 * HWSZ];
    xt[idx] = v;
}

// ---------------- deformable gather + per-pixel [64 x 576] contraction --------------
// 1 thread = 1 pixel. Loop over 16 deform groups; per group: stage the 64x36 weight
// slice in smem, sample 9 taps x 4 channels (float4 gathers), accumulate 64 outputs.
__global__ __launch_bounds__(128, 3)
void deform_kernel(const float4* __restrict__ xt,     // [B,16,HW] float4
                   const float* __restrict__ o,       // [B,432,HW]
                   const float* __restrict__ flow,    // [B,2,HW]
                   const float* __restrict__ weight,  // [64,64,9] = [o][g*4+c][k]
                   float* __restrict__ out) {         // [B,64,HW]
    __shared__ __align__(16) float s_w[64 * 36];

    const int tid = threadIdx.x;
    const int b = blockIdx.y;
    const int p = blockIdx.x * 128 + tid;
    const int h = p >> 7;
    const int w = p & 127;

    const float* ob = o + (size_t)b * 432 * HWSZ + p;
    const float fy = flow[((size_t)b * 2 + 1) * HWSZ + p];  // flow[:, ::-1] -> y comp = flow ch1
    const float fx = flow[((size_t)b * 2 + 0) * HWSZ + p];

    float acc[64];
#pragma unroll
    for (int i = 0; i < 64; i++) acc[i] = 0.f;

    for (int g = 0; g < 16; g++) {
        __syncthreads();
        // weight[o][g*4+c][k] -> s_w[o*36 + c*9 + k]
        for (int idx = tid; idx < 64 * 36; idx += 128) {
            int oo = idx / 36;
            int m = idx % 36;
            s_w[idx] = weight[(size_t)oo * 576 + g * 36 + m];
        }
        __syncthreads();

        const float4* xg = xt + (size_t)(b * 16 + g) * HWSZ;
        float val[36];

#pragma unroll
        for (int k = 0; k < 9; k++) {
            float lo_y = ob[(size_t)(g * 18 + 2 * k) * HWSZ];
            float lo_x = ob[(size_t)(g * 18 + 2 * k + 1) * HWSZ];
            float lo_m = ob[(size_t)(288 + g * 9 + k) * HWSZ];

            float offy = 10.f * tanhf(lo_y) + fy;
            float offx = 10.f * tanhf(lo_x) + fx;
            float msk = 1.f / (1.f + expf(-lo_m));

            float py = (float)(h + (k / 3) - 1) + offy;
            float px = (float)(w + (k % 3) - 1) + offx;

            float y0f = floorf(py);
            float x0f = floorf(px);
            float wy = py - y0f;
            float wx = px - x0f;
            int y0 = (int)y0f;
            int x0 = (int)x0f;

            bool y0v = (y0 >= 0) && (y0 < HH);
            bool y1v = (y0 + 1 >= 0) && (y0 + 1 < HH);
            bool x0v = (x0 >= 0) && (x0 < WW);
            bool x1v = (x0 + 1 >= 0) && (x0 + 1 < WW);

            float4 v00 = make_float4(0.f, 0.f, 0.f, 0.f);
            float4 v01 = v00, v10 = v00, v11 = v00;
            if (y0v && x0v) v00 = __ldg(&xg[y0 * WW + x0]);
            if (y0v && x1v) v01 = __ldg(&xg[y0 * WW + x0 + 1]);
            if (y1v && x0v) v10 = __ldg(&xg[(y0 + 1) * WW + x0]);
            if (y1v && x1v) v11 = __ldg(&xg[(y0 + 1) * WW + x0 + 1]);

            float w00 = (1.f - wy) * (1.f - wx);
            float w01 = (1.f - wy) * wx;
            float w10 = wy * (1.f - wx);
            float w11 = wy * wx;

            val[0 * 9 + k] = msk * (w00 * v00.x + w01 * v01.x + w10 * v10.x + w11 * v11.x);
            val[1 * 9 + k] = msk * (w00 * v00.y + w01 * v01.y + w10 * v10.y + w11 * v11.y);
            val[2 * 9 + k] = msk * (w00 * v00.z + w01 * v01.z + w10 * v10.z + w11 * v11.z);
            val[3 * 9 + k] = msk * (w00 * v00.w + w01 * v01.w + w10 * v10.w + w11 * v11.w);
        }

        const float4* sw4 = (const float4*)s_w;
#pragma unroll
        for (int oo = 0; oo < 64; oo++) {
#pragma unroll
            for (int m4 = 0; m4 < 9; m4++) {
                float4 w4 = sw4[oo * 9 + m4];
                acc[oo] = fmaf(val[m4 * 4 + 0], w4.x, acc[oo]);
                acc[oo] = fmaf(val[m4 * 4 + 1], w4.y, acc[oo]);
                acc[oo] = fmaf(val[m4 * 4 + 2], w4.z, acc[oo]);
                acc[oo] = fmaf(val[m4 * 4 + 3], w4.w, acc[oo]);
            }
        }
    }

#pragma unroll
    for (int oo = 0; oo < 64; oo++)
        out[((size_t)b * 64 + oo) * HWSZ + p] = acc[oo];
}

// ---------------- launch ----------------
extern "C" void kernel_launch(void* const* d_in, const int* in_sizes, int n_in,
                              void* d_out, int out_size) {
    const float* x          = (const float*)d_in[0];
    const float* extra_feat = (const float*)d_in[1];
    const float* flow       = (const float*)d_in[2];
    const float* w1         = (const float*)d_in[3];
    const float* b1         = (const float*)d_in[4];
    const float* w2         = (const float*)d_in[5];
    const float* b2         = (const float*)d_in[6];
    const float* w3         = (const float*)d_in[7];
    const float* b3         = (const float*)d_in[8];
    const float* weight     = (const float*)d_in[9];
    float* out = (float*)d_out;

    float *h1, *h2, *obuf;
    float4* xt;
    cudaGetSymbolAddress((void**)&h1, g_h1);
    cudaGetSymbolAddress((void**)&h2, g_h2);
    cudaGetSymbolAddress((void**)&obuf, g_o);
    cudaGetSymbolAddress((void**)&xt, g_xt);

    // x -> channels-last-per-group copy (for float4 gathers)
    transpose_x_kernel<<<(2 * 16 * HWSZ + 255) / 256, 256>>>(x, xt);

    // conv1: 128 -> 64, leaky
    conv3x3_kernel<true><<<dim3(16, 64 / OCB, 2), 256>>>(extra_feat, w1, b1, h1, 128, 64);
    // conv2: 64 -> 64, leaky
    conv3x3_kernel<true><<<dim3(16, 64 / OCB, 2), 256>>>(h1, w2, b2, h2, 64, 64);
    // conv3: 64 -> 432, linear
    conv3x3_kernel<false><<<dim3(16, 432 / OCB, 2), 256>>>(h2, w3, b3, obuf, 64, 432);

    // deformable gather + contraction
    deform_kernel<<<dim3(HWSZ / 128, 2), 128>>>(xt, obuf, flow, weight, out);
}